// round 10
// baseline (speedup 1.0000x reference)
#include <cuda_runtime.h>
#include <math.h>

// ---------------- scratch (static, no allocations) ----------------
#define MAXN  65536
#define TABK  512
#define TABXMAX 16.0f
#define TABB  (TABK / 8)   // table blocks: warp per entry, 8 warps/block
#define PREB  20           // p-precompute blocks
#define ZPB   296          // zero/pack grid-stride blocks

__device__ float4 g_C0[MAXN * 10];   // q0 per (n,a): (G0, G1*Y1x, G1*Y1y, G1*Y1z)
__device__ float4 g_C1[MAXN * 10];   // q1 per (n,a): 4 of the l=2 coeffs
__device__ float4 g_C2[MAXN * 5];    // viewed as float2[MAXN*10]: (c8, count)
__device__ float4 g_pa[MAXN];        // packed (pos.xyz, A-as-bits)
__device__ float4 g_tab[TABK];       // gates(length) table, PATH_NORM folded
__device__ float  g_P[4800];         // P[l(3)][a_dst(10)][a_src(10)][w(16)]

__device__ __forceinline__ float silu_f(float x) {
    return x / (1.0f + __expf(-x));
}

struct TableSmem {
    float sW1[16 * 64];
    float sW2[64 * 64];
    float sW3[3 * 64];
    float sB1[64], sB2[64];
    float sG[8][64];
};
struct PSmem {
    float hS[10][64];
    float AiS[10][8];
};

// ---------------- fused prep: table | P | zero+pack (grid-stride) ----------------
__global__ void __launch_bounds__(256)
prep_kernel(const float* __restrict__ pos, const int* __restrict__ A,
            const float* __restrict__ embT,
            const float* __restrict__ aw1, const float* __restrict__ ab1,
            const float* __restrict__ aw2, const float* __restrict__ ab2,
            const float* __restrict__ fw1, const float* __restrict__ fb1,
            const float* __restrict__ fw2, const float* __restrict__ fb2,
            const float* __restrict__ fw3, const float* __restrict__ fb3,
            const float* __restrict__ tpw,
            int N)
{
    __shared__ __align__(16) char smem_raw[sizeof(TableSmem)];
    int bid = blockIdx.x;
    int tid = threadIdx.x;

    if (bid < TABB) {
        // -------- gate table, warp per entry --------
        TableSmem& S = *reinterpret_cast<TableSmem*>(smem_raw);
        for (int i = tid; i < 16 * 64; i += 256) S.sW1[i] = fw1[i];
        for (int i = tid; i < 64 * 64; i += 256) S.sW2[i] = fw2[i];
        if (tid < 64) {
            S.sW3[tid]       = fw3[tid * 15 + 0];
            S.sW3[64 + tid]  = fw3[tid * 15 + 3];
            S.sW3[128 + tid] = fw3[tid * 15 + 9];
            S.sB1[tid] = fb1[tid];
            S.sB2[tid] = fb2[tid];
        }
        __syncthreads();

        int warp = tid >> 5, lane = tid & 31;
        int entry = bid * 8 + warp;
        float x = (TABXMAX * (float)entry) / (float)(TABK - 1);

        float ev = 0.0f;
        if (lane < 16) {
            const float step = 5.0f / 17.0f;
            float v = 5.0f * (float)(lane + 1) / 17.0f;
            float d = (x - v) / step;
            ev = __expf(-d * d) * (4.0f / 1.12f);
        }

        float a0 = S.sB1[lane], a1 = S.sB1[lane + 32];
#pragma unroll
        for (int k = 0; k < 16; k++) {
            float e = __shfl_sync(0xffffffffu, ev, k);
            a0 += e * S.sW1[k * 64 + lane];
            a1 += e * S.sW1[k * 64 + lane + 32];
        }
        S.sG[warp][lane]      = silu_f(a0);
        S.sG[warp][lane + 32] = silu_f(a1);
        __syncwarp();

        float b0 = S.sB2[lane], b1 = S.sB2[lane + 32];
#pragma unroll
        for (int k = 0; k < 64; k++) {
            float g = S.sG[warp][k];
            b0 += g * S.sW2[k * 64 + lane];
            b1 += g * S.sW2[k * 64 + lane + 32];
        }
        float h0 = silu_f(b0), h1 = silu_f(b1);

        float pa = h0 * S.sW3[lane]       + h1 * S.sW3[lane + 32];
        float pb = h0 * S.sW3[64 + lane]  + h1 * S.sW3[64 + lane + 32];
        float pc = h0 * S.sW3[128 + lane] + h1 * S.sW3[128 + lane + 32];
#pragma unroll
        for (int off = 16; off > 0; off >>= 1) {
            pa += __shfl_xor_sync(0xffffffffu, pa, off);
            pb += __shfl_xor_sync(0xffffffffu, pb, off);
            pc += __shfl_xor_sync(0xffffffffu, pc, off);
        }
        if (lane == 0) {
            const float PN = 0.125f;
            g_tab[entry] = make_float4((pa + __ldg(fb3 + 0)) * PN,
                                       (pb + __ldg(fb3 + 3)) * PN,
                                       (pc + __ldg(fb3 + 9)) * PN, 0.0f);
        }
        return;
    }

    if (bid < TABB + PREB) {
        // -------- P precompute (PREB blocks x 240 entries) --------
        PSmem& S = *reinterpret_cast<PSmem*>(smem_raw);
        for (int idx = tid; idx < 640; idx += 256) {
            int a = idx >> 6, j = idx & 63;
            float acc = ab1[j];
#pragma unroll
            for (int k = 0; k < 16; k++) acc += embT[a * 16 + k] * aw1[k * 64 + j];
            S.hS[a][j] = silu_f(acc);
        }
        __syncthreads();
        if (tid < 80) {
            int a = tid / 8, m = tid % 8;
            float acc = ab2[m];
#pragma unroll
            for (int j = 0; j < 64; j++) acc += S.hS[a][j] * aw2[j * 8 + m];
            S.AiS[a][m] = acc;
        }
        __syncthreads();

        if (tid < 240) {
            int idx = (bid - TABB) * 240 + tid;   // [0, 4800)
            int w  = idx & 15;
            int as = (idx >> 4) % 10;
            int ad = ((idx >> 4) / 10) % 10;
            int l  = idx / 1600;
            int path = (l == 0) ? 0 : (l == 1) ? 3 : 9;
            const float* W = tpw + path * 1024;
            float acc = 0.0f;
#pragma unroll
            for (int u = 0; u < 8; u++) {
                float mu = 0.0f;
#pragma unroll
                for (int v = 0; v < 8; v++)
                    mu += S.AiS[ad][v] * W[(u * 8 + v) * 16 + w];
                acc += S.AiS[as][u] * mu;
            }
            g_P[idx] = acc;
        }
        return;
    }

    // -------- zero C0/C1/C2 + pack pos+A, grid-stride --------
    {
        int t0   = (bid - TABB - PREB) * 256 + tid;
        int nstr = ZPB * 256;
        int n0 = N * 10, n1 = N * 10, n2 = N * 5;
        int tot = n0 + n1 + n2 + N;
        const float4 z4 = make_float4(0.f, 0.f, 0.f, 0.f);
        for (int i = t0; i < tot; i += nstr) {
            if (i < n0) {
                g_C0[i] = z4;
            } else if (i < n0 + n1) {
                g_C1[i - n0] = z4;
            } else if (i < n0 + n1 + n2) {
                g_C2[i - n0 - n1] = z4;
            } else {
                int n = i - n0 - n1 - n2;
                g_pa[n] = make_float4(pos[3 * n + 0], pos[3 * n + 1], pos[3 * n + 2],
                                      __int_as_float(A[n]));
            }
        }
    }
}

// ---------------- edge scatter: Catmull-Rom gate interp, 10 atomic lanes ----------------
__global__ void __launch_bounds__(256)
edge_kernel(const int*   __restrict__ esrc,
            const int*   __restrict__ edst,
            const float* __restrict__ shifts,
            const int*   __restrict__ batch,
            const float* __restrict__ cell,
            int E)
{
    int e = blockIdx.x * 256 + threadIdx.x;
    if (e >= E) return;

    int s0 = esrc[e];
    int d0 = edst[e];

    float4 ps = __ldg(&g_pa[s0]);
    float4 pd = __ldg(&g_pa[d0]);

    float dx = pd.x - ps.x;
    float dy = pd.y - ps.y;
    float dz = pd.z - ps.z;

    float shx = shifts[e * 3 + 0];
    float shy = shifts[e * 3 + 1];
    float shz = shifts[e * 3 + 2];
    if (shx != 0.0f || shy != 0.0f || shz != 0.0f) {
        const float* c = cell + (size_t)batch[s0] * 9;
        dx += shx * c[0] + shy * c[3] + shz * c[6];
        dy += shx * c[1] + shy * c[4] + shz * c[7];
        dz += shx * c[2] + shy * c[5] + shz * c[8];
    }

    float len  = sqrtf(dx * dx + dy * dy + dz * dz);
    float rinv = 1.0f / fmaxf(len, 1e-8f);
    float nx = dx * rinv, ny = dy * rinv, nz = dz * rinv;

    // Catmull-Rom cubic gate interpolation (table flat at tail -> clamping exact)
    float t  = len * ((float)(TABK - 1) / TABXMAX);
    int   i0 = (int)t;
    i0 = i0 < (TABK - 2) ? i0 : (TABK - 2);
    float fr = t - (float)i0;
    int im1 = i0 > 0 ? i0 - 1 : 0;
    int ip2 = i0 + 2 < TABK ? i0 + 2 : TABK - 1;

    float4 pm = __ldg(&g_tab[im1]);
    float4 p0 = __ldg(&g_tab[i0]);
    float4 p1 = __ldg(&g_tab[i0 + 1]);
    float4 p2 = __ldg(&g_tab[ip2]);

    float G0, G1, G2;
    {
        // component-wise Hermite with CR slopes
        float m0, m1, d, c2c, c3c;
        m0 = 0.5f * (p1.x - pm.x); m1 = 0.5f * (p2.x - p0.x); d = p1.x - p0.x;
        c2c = 3.0f * d - 2.0f * m0 - m1; c3c = m0 + m1 - 2.0f * d;
        G0 = p0.x + fr * (m0 + fr * (c2c + fr * c3c));
        m0 = 0.5f * (p1.y - pm.y); m1 = 0.5f * (p2.y - p0.y); d = p1.y - p0.y;
        c2c = 3.0f * d - 2.0f * m0 - m1; c3c = m0 + m1 - 2.0f * d;
        G1 = p0.y + fr * (m0 + fr * (c2c + fr * c3c));
        m0 = 0.5f * (p1.z - pm.z); m1 = 0.5f * (p2.z - p0.z); d = p1.z - p0.z;
        c2c = 3.0f * d - 2.0f * m0 - m1; c3c = m0 + m1 - 2.0f * d;
        G2 = p0.z + fr * (m0 + fr * (c2c + fr * c3c));
    }

    const float SQ3   = 1.7320508075688772f;
    const float SQ15  = 3.872983346207417f;
    const float SQ5H  = 1.118033988749895f;
    const float SQ15H = 1.9364916731037085f;

    float4 q0 = make_float4(G0,
                            G1 * (SQ3 * nx),
                            G1 * (SQ3 * ny),
                            G1 * (SQ3 * nz));
    float4 q1 = make_float4(G2 * (SQ15 * nx * ny),
                            G2 * (SQ15 * ny * nz),
                            G2 * (SQ5H * (3.0f * nz * nz - 1.0f)),
                            G2 * (SQ15 * nx * nz));
    float2 q2 = make_float2(G2 * (SQ15H * (nx * nx - ny * ny)), 1.0f);

    int a = __float_as_int(ps.w);
    size_t base = (size_t)d0 * 10 + a;
    atomicAdd(&g_C0[base], q0);
    atomicAdd(&g_C1[base], q1);
    atomicAdd(((float2*)g_C2) + base, q2);
}

// ---------------- node output: 2 threads per node (w-halves), all three l ----------------
__global__ void __launch_bounds__(128)
node_out_kernel(float* __restrict__ out, int N)
{
    // Psm[(l*160 + a*16 + w)*10 + at]
    __shared__ float Psm[4800];
    for (int i = threadIdx.x; i < 4800; i += 128) {
        int w  = i & 15;
        int as = (i >> 4) % 10;
        int ad = ((i >> 4) / 10) % 10;
        int l  = i / 1600;
        Psm[(l * 160 + as * 16 + w) * 10 + ad] = g_P[i];
    }
    __syncthreads();

    int t = blockIdx.x * 128 + threadIdx.x;
    int n = t >> 1;
    int q = t & 1;           // w-half: w in [8q, 8q+8)
    if (n >= N) return;

    int at = __float_as_int(__ldg(&g_pa[n]).w);
    const float4*  Crow0 = g_C0 + (size_t)n * 10;
    const float4*  Crow1 = g_C1 + (size_t)n * 10;
    const float2*  Crow2 = ((const float2*)g_C2) + (size_t)n * 10;
    int wb = 8 * q;

    float acc0[8], acc1[24], acc2[40];
#pragma unroll
    for (int j = 0; j < 8; j++)  acc0[j] = 0.0f;
#pragma unroll
    for (int j = 0; j < 24; j++) acc1[j] = 0.0f;
#pragma unroll
    for (int j = 0; j < 40; j++) acc2[j] = 0.0f;

    float cnt = 0.0f;

#pragma unroll
    for (int a = 0; a < 10; a++) {
        float4 c0 = Crow0[a];
        float4 c1 = Crow1[a];
        float2 c2 = Crow2[a];
        cnt += c2.y;

        const float* P0 = Psm + (a * 16 + wb) * 10 + at;
        const float* P1 = Psm + (160 + a * 16 + wb) * 10 + at;
        const float* P2 = Psm + (320 + a * 16 + wb) * 10 + at;
#pragma unroll
        for (int w = 0; w < 8; w++) {
            float p0 = P0[w * 10];
            float p1 = P1[w * 10];
            float p2 = P2[w * 10];
            acc0[w] += p0 * c0.x;
            acc1[w * 3 + 0] += p1 * c0.y;
            acc1[w * 3 + 1] += p1 * c0.z;
            acc1[w * 3 + 2] += p1 * c0.w;
            acc2[w * 5 + 0] += p2 * c1.x;
            acc2[w * 5 + 1] += p2 * c1.y;
            acc2[w * 5 + 2] += p2 * c1.z;
            acc2[w * 5 + 3] += p2 * c1.w;
            acc2[w * 5 + 4] += p2 * c2.x;
        }
    }

    float inv = 1.0f / fmaxf(cnt, 1.0f);
    float* row = out + (size_t)n * 144;

    // l0: floats [8q, 8q+8)  -> 2 aligned float4
    {
        float4* r4 = (float4*)(row) + 2 * q;
#pragma unroll
        for (int j = 0; j < 2; j++)
            r4[j] = make_float4(acc0[4*j]*inv, acc0[4*j+1]*inv, acc0[4*j+2]*inv, acc0[4*j+3]*inv);
    }
    // l1: floats [16+24q, +24) -> 6 aligned float4
    {
        float4* r4 = (float4*)(row + 16 + 24 * q);
#pragma unroll
        for (int j = 0; j < 6; j++)
            r4[j] = make_float4(acc1[4*j]*inv, acc1[4*j+1]*inv, acc1[4*j+2]*inv, acc1[4*j+3]*inv);
    }
    // l2: floats [64+40q, +40) -> 10 aligned float4
    {
        float4* r4 = (float4*)(row + 64 + 40 * q);
#pragma unroll
        for (int j = 0; j < 10; j++)
            r4[j] = make_float4(acc2[4*j]*inv, acc2[4*j+1]*inv, acc2[4*j+2]*inv, acc2[4*j+3]*inv);
    }
}

// ---------------- launch ----------------
extern "C" void kernel_launch(void* const* d_in, const int* in_sizes, int n_in,
                              void* d_out, int out_size)
{
    const float* pos    = (const float*)d_in[0];
    const int*   A      = (const int*)  d_in[1];
    const int*   batch  = (const int*)  d_in[2];
    const int*   esrc   = (const int*)  d_in[3];
    const int*   edst   = (const int*)  d_in[4];
    const float* shifts = (const float*)d_in[5];
    const float* cell   = (const float*)d_in[6];
    const float* embT   = (const float*)d_in[7];
    const float* aw1    = (const float*)d_in[8];
    const float* ab1    = (const float*)d_in[9];
    const float* aw2    = (const float*)d_in[10];
    const float* ab2    = (const float*)d_in[11];
    const float* fw1    = (const float*)d_in[12];
    const float* fb1    = (const float*)d_in[13];
    const float* fw2    = (const float*)d_in[14];
    const float* fb2    = (const float*)d_in[15];
    const float* fw3    = (const float*)d_in[16];
    const float* fb3    = (const float*)d_in[17];
    const float* tpw    = (const float*)d_in[18];

    int N = in_sizes[0] / 3;
    int E = in_sizes[3];
    float* out = (float*)d_out;

    prep_kernel<<<TABB + PREB + ZPB, 256>>>(pos, A, embT, aw1, ab1, aw2, ab2,
                                            fw1, fb1, fw2, fb2, fw3, fb3, tpw, N);
    edge_kernel<<<(E + 255) / 256, 256>>>(esrc, edst, shifts, batch, cell, E);
    node_out_kernel<<<(2 * N + 127) / 128, 128>>>(out, N);
}